// round 7
// baseline (speedup 1.0000x reference)
#include <cuda_runtime.h>

#define NCH   96
#define NRF   25
#define HALF  12
#define IMH   55
#define IMW   55
#define NB    128
#define POS   (IMH*IMW)          // 3025
#define MAXPLANES 6
#define MAXTAPS   40
#define KELEMS (NRF*NRF)         // 625
#define KCHUNKS 20

struct __align__(8) Tap { short dr, dc; float w; };

// ---- device-global state (static scratch; no allocations) ----
__device__ int   g_cnt_ch[NCH];
__device__ Tap   g_taps_ch[NCH][MAXTAPS];
__device__ int   g_nplanes;
__device__ int   g_plane_ch[MAXPLANES];
__device__ int   g_pcol4[MAXPLANES];   // ch>>2 : float4 column of the plane's channel
__device__ int   g_pcomp[MAXPLANES];   // ch&3  : component within the float4
__device__ int   g_chplane[NCH];       // plane idx (0 for inactive)
__device__ float g_chmask[NCH];        // 1.0 active, 0.0 inactive
__device__ float g_lat[NB][MAXPLANES][POS];   // 9.3 MB scratch

// ---------------------------------------------------------------------------
// 1) Extract: one warp per channel; preloaded MLP=20, ballot ranks.
// ---------------------------------------------------------------------------
__global__ void __launch_bounds__(32) extract_kernel(const float* __restrict__ k) {
    const int c = blockIdx.x;
    const int lane = threadIdx.x;
    float v[KCHUNKS];
    #pragma unroll
    for (int j = 0; j < KCHUNKS; j++) {
        const int i = j * 32 + lane;
        v[j] = (i < KELEMS) ? __ldg(&k[c * KELEMS + i]) : 0.0f;
    }
    int total = 0;
    #pragma unroll
    for (int j = 0; j < KCHUNKS; j++) {
        const int i = j * 32 + lane;
        const unsigned m = __ballot_sync(0xFFFFFFFFu, v[j] != 0.0f);
        if (v[j] != 0.0f) {
            const int rank = total + __popc(m & ((1u << lane) - 1u));
            if (rank < MAXTAPS) {
                Tap t;
                t.dr = (short)(i / NRF - HALF);
                t.dc = (short)(i % NRF - HALF);
                t.w  = v[j];
                g_taps_ch[c][rank] = t;
            }
        }
        total += __popc(m);
    }
    if (lane == 0) g_cnt_ch[c] = (total < MAXTAPS) ? total : MAXTAPS;
}

// ---------------------------------------------------------------------------
// 2) Plan: tiny serial pass -> plane list + per-channel mask/plane.
// ---------------------------------------------------------------------------
__global__ void plan_kernel() {
    __shared__ int pid[NCH];
    const int tid = threadIdx.x;           // 128 threads
    if (tid == 0) {
        int np = 0;
        for (int cc = 0; cc < NCH; cc++) {
            if (g_cnt_ch[cc] > 0 && np < MAXPLANES) {
                pid[cc] = np;
                g_plane_ch[np] = cc;
                g_pcol4[np] = cc >> 2;
                g_pcomp[np] = cc & 3;
                np++;
            } else pid[cc] = -1;
        }
        g_nplanes = np;
    }
    __syncthreads();
    if (tid < NCH) {
        const int p = pid[tid];
        g_chplane[tid] = (p >= 0) ? p : 0;
        g_chmask[tid]  = (p >= 0) ? 1.0f : 0.0f;
    }
}

// ---------------------------------------------------------------------------
// 3) Lateral: block = (row-quarter, image), all 6 planes together.
//    Gather via per-plane float4 loads (16B/sector used), taps in smem,
//    coalesced g_lat write. 512 blocks x 256 thr, 4 blocks/SM -> one wave.
// ---------------------------------------------------------------------------
#define LT      256
#define QROWS   14
#define MAXLROWS (QROWS + 2*HALF)          // 38
#define LIMG    (MAXLROWS * IMW)           // 2090

__global__ void __launch_bounds__(LT, 4) lat_kernel(const float* __restrict__ x) {
    __shared__ float s_img[MAXPLANES][LIMG];    // 50160 B
    __shared__ Tap   s_taps[MAXPLANES][MAXTAPS];
    __shared__ int   s_pcol4[MAXPLANES], s_pcomp[MAXPLANES], s_nt[MAXPLANES];

    const int tid = threadIdx.x;
    const int q   = blockIdx.x;            // 0..3
    const int n   = blockIdx.y;
    const int np  = g_nplanes;

    const int r0 = q * QROWS;
    const int r1 = (r0 + QROWS < IMH) ? r0 + QROWS : IMH;
    const int lo = (r0 - HALF > 0) ? r0 - HALF : 0;
    const int hi = (r1 + HALF < IMH) ? r1 + HALF : IMH;
    const int nrows = hi - lo;

    if (tid < MAXPLANES) {
        const bool on = tid < np;
        const int ch = on ? g_plane_ch[tid] : 0;
        s_pcol4[tid] = on ? g_pcol4[tid] : 0;
        s_pcomp[tid] = on ? g_pcomp[tid] : 0;
        s_nt[tid]    = on ? g_cnt_ch[ch] : 0;
    }
    for (int i = tid; i < MAXPLANES * MAXTAPS; i += LT) {
        const int p = i / MAXTAPS;
        ((Tap*)s_taps)[i] = g_taps_ch[(p < np) ? g_plane_ch[p] : 0][i % MAXTAPS];
    }
    __syncthreads();

    // ---- Gather: per position, 6 independent float4 loads (one per plane) ----
    const float4* xim = (const float4*)x + (long)(n * POS + lo * IMW) * (NCH / 4);
    const int tot = nrows * IMW;
    for (int pos = tid; pos < tot; pos += LT) {
        const int b = pos * (NCH / 4);
        #pragma unroll
        for (int p = 0; p < MAXPLANES; p++) {
            if (p < np) {
                const float4 v = __ldg(&xim[b + s_pcol4[p]]);
                const int comp = s_pcomp[p];
                const float val = (comp == 0) ? v.x : (comp == 1) ? v.y
                                : (comp == 2) ? v.z : v.w;
                s_img[p][pos] = val;
            }
        }
    }
    __syncthreads();

    // ---- Taps -> g_lat (coalesced) ----
    const int orows = r1 - r0;
    const int tot2 = np * orows * IMW;
    for (int j = tid; j < tot2; j += LT) {
        const int p   = j / (orows * IMW);
        const int rem = j - p * (orows * IMW);
        const int hl  = rem / IMW;
        const int w   = rem - hl * IMW;
        const int h   = r0 + hl;
        float acc = 0.0f;
        const int nt = s_nt[p];
        for (int t = 0; t < nt; t++) {
            const Tap tp = s_taps[p][t];
            const int hh = h + tp.dr;
            const int ww = w + tp.dc;
            if ((unsigned)hh < (unsigned)IMH && (unsigned)ww < (unsigned)IMW)
                acc += tp.w * s_img[p][(hh - lo) * IMW + ww];
        }
        g_lat[n][p][h * IMW + w] = acc;
    }
}

// ---------------------------------------------------------------------------
// 4) Stream: persistent row-tile kernel, one wave, streaming cache hints.
// ---------------------------------------------------------------------------
#define STR_THREADS 240
#define STR_BLOCKS  1184              // 148 SMs * 8 blocks
#define NTILES      (NB * IMH)        // 7040 row tiles
#define ROWV4       (IMW * NCH / 4)   // 1320 float4 per row

__global__ void __launch_bounds__(STR_THREADS, 8) stream_kernel(
    const float* __restrict__ x, float* __restrict__ out)
{
    __shared__ float s_lat[MAXPLANES * IMW];   // 1.3 KB

    const int tid = threadIdx.x;
    const int np  = g_nplanes;

    const int c4   = tid % 24;
    const int pos0 = tid / 24;        // 0..9
    const int c0   = c4 * 4;
    const float m0 = g_chmask[c0+0], m1 = g_chmask[c0+1], m2 = g_chmask[c0+2], m3 = g_chmask[c0+3];
    const int   o0 = g_chplane[c0+0] * IMW, o1 = g_chplane[c0+1] * IMW,
                o2 = g_chplane[c0+2] * IMW, o3 = g_chplane[c0+3] * IMW;

    for (int t = blockIdx.x; t < NTILES; t += STR_BLOCKS) {
        const int n = t / IMH;
        const int h = t - n * IMH;

        for (int j = tid; j < np * IMW; j += STR_THREADS) {
            const int p = j / IMW;
            const int w = j - p * IMW;
            s_lat[j] = __ldcs(&g_lat[n][p][h * IMW + w]);
        }
        __syncthreads();

        const int base = (n * IMH + h) * ROWV4;
        const float4* x4 = (const float4*)x + base;
        float4*       o4 = (float4*)out + base;

        #pragma unroll
        for (int k = 0; k < 6; k++) {             // 1320 = 240*5.5
            const int i   = tid + 240 * k;
            const int pos = pos0 + 10 * k;
            if (i < ROWV4) {
                float4 v = __ldcs(&x4[i]);
                v.x += m0 * s_lat[o0 + pos];
                v.y += m1 * s_lat[o1 + pos];
                v.z += m2 * s_lat[o2 + pos];
                v.w += m3 * s_lat[o3 + pos];
                __stcs(&o4[i], v);
            }
        }
        __syncthreads();
    }
}

extern "C" void kernel_launch(void* const* d_in, const int* in_sizes, int n_in,
                              void* d_out, int out_size) {
    const float* x = (const float*)d_in[0];   // [128,55,55,96] f32
    const float* k = (const float*)d_in[1];   // [96,25,25] f32
    float* out = (float*)d_out;
    (void)in_sizes; (void)n_in; (void)out_size;

    extract_kernel<<<NCH, 32>>>(k);
    plan_kernel<<<1, 128>>>();
    lat_kernel<<<dim3(4, NB), LT>>>(x);
    stream_kernel<<<STR_BLOCKS, STR_THREADS>>>(x, out);
}

// round 10
// speedup vs baseline: 1.9169x; 1.9169x over previous
#include <cuda_runtime.h>

#define NCH   96
#define NRF   25
#define HALF  12
#define IMH   55
#define IMW   55
#define NB    128
#define POS   (IMH*IMW)          // 3025
#define POSP  3028               // padded to multiple of 4 (float4 alignment)
#define NG4   757                // POSP/4 float4 groups per plane
#define MAXPLANES 6
#define MAXTAPS   40
#define KELEMS (NRF*NRF)         // 625
#define KCHUNKS 20

struct __align__(8) Tap { short dr, dc; float w; };

// ---- device-global state (static scratch; no allocations) ----
__device__ int   g_cnt_ch[NCH];
__device__ Tap   g_taps_ch[NCH][MAXTAPS];
__device__ int   g_nplanes;
__device__ int   g_plane_ch[MAXPLANES];
__device__ int   g_chplane[NCH];       // plane idx (0 for inactive)
__device__ float g_chmask[NCH];        // 1.0 active, 0.0 inactive
__device__ float g_planes[NB][MAXPLANES][POSP];  // compact planes, 9.3 MB
__device__ float g_lat[NB][MAXPLANES][POS];      // lateral sums,  9.3 MB

// ---------------------------------------------------------------------------
// 1) Extract: one warp per channel; preloaded MLP=20, ballot ranks.
// ---------------------------------------------------------------------------
__global__ void __launch_bounds__(32) extract_kernel(const float* __restrict__ k) {
    const int c = blockIdx.x;
    const int lane = threadIdx.x;
    float v[KCHUNKS];
    #pragma unroll
    for (int j = 0; j < KCHUNKS; j++) {
        const int i = j * 32 + lane;
        v[j] = (i < KELEMS) ? __ldg(&k[c * KELEMS + i]) : 0.0f;
    }
    int total = 0;
    #pragma unroll
    for (int j = 0; j < KCHUNKS; j++) {
        const int i = j * 32 + lane;
        const unsigned m = __ballot_sync(0xFFFFFFFFu, v[j] != 0.0f);
        if (v[j] != 0.0f) {
            const int rank = total + __popc(m & ((1u << lane) - 1u));
            if (rank < MAXTAPS) {
                Tap t;
                t.dr = (short)(i / NRF - HALF);
                t.dc = (short)(i % NRF - HALF);
                t.w  = v[j];
                g_taps_ch[c][rank] = t;
            }
        }
        total += __popc(m);
    }
    if (lane == 0) g_cnt_ch[c] = (total < MAXTAPS) ? total : MAXTAPS;
}

// ---------------------------------------------------------------------------
// 2) Plan: tiny serial pass -> plane list + per-channel mask/plane.
// ---------------------------------------------------------------------------
__global__ void plan_kernel() {
    __shared__ int pid[NCH];
    const int tid = threadIdx.x;           // 128 threads
    if (tid == 0) {
        int np = 0;
        for (int cc = 0; cc < NCH; cc++) {
            if (g_cnt_ch[cc] > 0 && np < MAXPLANES) {
                pid[cc] = np;
                g_plane_ch[np] = cc;
                np++;
            } else pid[cc] = -1;
        }
        g_nplanes = np;
    }
    __syncthreads();
    if (tid < NCH) {
        const int p = pid[tid];
        g_chplane[tid] = (p >= 0) ? p : 0;
        g_chmask[tid]  = (p >= 0) ? 1.0f : 0.0f;
    }
}

// ---------------------------------------------------------------------------
// 3) Gather: pure scatter -> compact transpose. No smem, no barriers.
//    Thread = one float4 group of one (image, plane): 4 independent scalar
//    LDGs (stride 384B) + one coalesced STG.128. Latency-tolerant huge grid.
// ---------------------------------------------------------------------------
#define GT 256
#define GTOTAL (NB * MAXPLANES * NG4)    // 581,376 threads

__global__ void __launch_bounds__(GT) gather_kernel(const float* __restrict__ x) {
    const int t = blockIdx.x * GT + threadIdx.x;
    if (t >= GTOTAL) return;
    const int n   = t / (MAXPLANES * NG4);
    const int rem = t - n * (MAXPLANES * NG4);
    const int p   = rem / NG4;
    const int g   = rem - p * NG4;
    if (p >= g_nplanes) return;
    const int ch  = g_plane_ch[p];
    const int pos = g * 4;
    const float* xb = x + (long)(n * POS + pos) * NCH + ch;
    float4 v;
    v.x = __ldg(xb);
    v.y = (pos + 1 < POS) ? __ldg(xb + NCH)     : 0.0f;
    v.z = (pos + 2 < POS) ? __ldg(xb + 2 * NCH) : 0.0f;
    v.w = (pos + 3 < POS) ? __ldg(xb + 3 * NCH) : 0.0f;
    *((float4*)&g_planes[n][p][0] + g) = v;
}

// ---------------------------------------------------------------------------
// 4) Latcomp: block per (image, plane). Coalesced float4 stage of the
//    compact plane -> smem, sparse taps, coalesced g_lat write.
// ---------------------------------------------------------------------------
#define LCT 256
#define LC_LD ((POS + LCT - 1) / LCT)    // 12

__global__ void __launch_bounds__(LCT, 8) latcomp_kernel() {
    __shared__ float s_img[POSP];        // 12.1 KB
    __shared__ Tap   s_taps[MAXTAPS];
    __shared__ int   s_nt;

    const int tid = threadIdx.x;
    const int n   = blockIdx.x;
    const int p   = blockIdx.y;
    if (p >= g_nplanes) return;          // uniform per block

    if (tid == 0) s_nt = g_cnt_ch[g_plane_ch[p]];
    if (tid < MAXTAPS) s_taps[tid] = g_taps_ch[g_plane_ch[p]][tid];

    // coalesced float4 stage: 757 groups
    const float4* src = (const float4*)&g_planes[n][p][0];
    for (int g = tid; g < NG4; g += LCT)
        *((float4*)s_img + g) = src[g];
    __syncthreads();

    const int nt = s_nt;
    #pragma unroll
    for (int j = 0; j < LC_LD; j++) {
        const int i = tid + j * LCT;
        if (i < POS) {
            const int h = i / IMW;
            const int w = i - h * IMW;
            float acc = 0.0f;
            for (int t = 0; t < nt; t++) {
                const Tap tp = s_taps[t];
                const int hh = h + tp.dr;
                const int ww = w + tp.dc;
                if ((unsigned)hh < (unsigned)IMH && (unsigned)ww < (unsigned)IMW)
                    acc += tp.w * s_img[hh * IMW + ww];
            }
            g_lat[n][p][i] = acc;
        }
    }
}

// ---------------------------------------------------------------------------
// 5) Stream: persistent row-tile kernel, one wave, streaming cache hints.
// ---------------------------------------------------------------------------
#define STR_THREADS 240
#define STR_BLOCKS  1184              // 148 SMs * 8 blocks
#define NTILES      (NB * IMH)        // 7040 row tiles
#define ROWV4       (IMW * NCH / 4)   // 1320 float4 per row

__global__ void __launch_bounds__(STR_THREADS, 8) stream_kernel(
    const float* __restrict__ x, float* __restrict__ out)
{
    __shared__ float s_lat[MAXPLANES * IMW];   // 1.3 KB

    const int tid = threadIdx.x;
    const int np  = g_nplanes;

    const int c4   = tid % 24;
    const int pos0 = tid / 24;        // 0..9
    const int c0   = c4 * 4;
    const float m0 = g_chmask[c0+0], m1 = g_chmask[c0+1], m2 = g_chmask[c0+2], m3 = g_chmask[c0+3];
    const int   o0 = g_chplane[c0+0] * IMW, o1 = g_chplane[c0+1] * IMW,
                o2 = g_chplane[c0+2] * IMW, o3 = g_chplane[c0+3] * IMW;

    for (int t = blockIdx.x; t < NTILES; t += STR_BLOCKS) {
        const int n = t / IMH;
        const int h = t - n * IMH;

        for (int j = tid; j < np * IMW; j += STR_THREADS) {
            const int p = j / IMW;
            const int w = j - p * IMW;
            s_lat[j] = __ldcs(&g_lat[n][p][h * IMW + w]);
        }
        __syncthreads();

        const int base = (n * IMH + h) * ROWV4;
        const float4* x4 = (const float4*)x + base;
        float4*       o4 = (float4*)out + base;

        #pragma unroll
        for (int k = 0; k < 6; k++) {             // 1320 = 240*5.5
            const int i   = tid + 240 * k;
            const int pos = pos0 + 10 * k;
            if (i < ROWV4) {
                float4 v = __ldcs(&x4[i]);
                v.x += m0 * s_lat[o0 + pos];
                v.y += m1 * s_lat[o1 + pos];
                v.z += m2 * s_lat[o2 + pos];
                v.w += m3 * s_lat[o3 + pos];
                __stcs(&o4[i], v);
            }
        }
        __syncthreads();
    }
}

extern "C" void kernel_launch(void* const* d_in, const int* in_sizes, int n_in,
                              void* d_out, int out_size) {
    const float* x = (const float*)d_in[0];   // [128,55,55,96] f32
    const float* k = (const float*)d_in[1];   // [96,25,25] f32
    float* out = (float*)d_out;
    (void)in_sizes; (void)n_in; (void)out_size;

    extract_kernel<<<NCH, 32>>>(k);
    plan_kernel<<<1, 128>>>();
    gather_kernel<<<(GTOTAL + GT - 1) / GT, GT>>>(x);
    latcomp_kernel<<<dim3(NB, MAXPLANES), LCT>>>();
    stream_kernel<<<STR_BLOCKS, STR_THREADS>>>(x, out);
}